// round 9
// baseline (speedup 1.0000x reference)
#include <cuda_runtime.h>
#include <cstdint>

// probs: float32 [50,50,50,50] -> 6,250,000 floats (row-major)
// X:     int32   [8,000,000, 4]
// out:   float32 [8,000,000]
//
// out[i] = probs[ ((X0*50 + X1)*50 + X2)*50 + X3 ]
//
// Best-known structure (R5) with deeper ILP:
//  - quarter-warp predicated gathers (8 active lanes/LDG: shorter replay
//    chains, 2 wf/cyc supply vs ~1 wf/cyc L1tex processing)
//  - __ldcg gathers (L2-only, no L1 fill), __ldcs X, __stcs out
//  - UNROLL=8: 8 independent X loads + 32 predicated gathers in flight per
//    thread to ride over L2 round-trip latency bubbles.

constexpr int THREADS = 256;
constexpr int UNROLL  = 8;
constexpr int TILE    = THREADS * UNROLL;   // 2048 samples per block

__global__ __launch_bounds__(THREADS) void joint_cat_gather8(
    const float* __restrict__ probs,
    const int4* __restrict__ X,
    float* __restrict__ out,
    int n)
{
    int base = blockIdx.x * TILE + threadIdx.x;
    int lane_group = (threadIdx.x & 31) >> 3;   // 0..3

    if (base + (UNROLL - 1) * THREADS < n) {
        // ---- fast path: full tile ----
        int4 x[UNROLL];
#pragma unroll
        for (int k = 0; k < UNROLL; k++)
            x[k] = __ldcs(&X[base + k * THREADS]);     // coalesced streaming loads

        int idx[UNROLL];
#pragma unroll
        for (int k = 0; k < UNROLL; k++)
            idx[k] = ((x[k].x * 50 + x[k].y) * 50 + x[k].z) * 50 + x[k].w;

        float r[UNROLL];
        // 32 predicated LDG.cg, 8 active lanes each; all independent.
#pragma unroll
        for (int j = 0; j < 4; j++) {
#pragma unroll
            for (int k = 0; k < UNROLL; k++) {
                if (lane_group == j)
                    r[k] = __ldcg(probs + idx[k]);     // L2-only gather
            }
        }

#pragma unroll
        for (int k = 0; k < UNROLL; k++)
            __stcs(&out[base + k * THREADS], r[k]);    // streaming stores
    } else {
        // ---- tail: per-element guard ----
#pragma unroll
        for (int k = 0; k < UNROLL; k++) {
            int i = base + k * THREADS;
            if (i < n) {
                int4 x = __ldcs(&X[i]);
                int idx = ((x.x * 50 + x.y) * 50 + x.z) * 50 + x.w;
                __stcs(&out[i], __ldcg(probs + idx));
            }
        }
    }
}

extern "C" void kernel_launch(void* const* d_in, const int* in_sizes, int n_in,
                              void* d_out, int out_size)
{
    const float* probs = (const float*)d_in[0];
    const int4* X = (const int4*)d_in[1];
    float* out = (float*)d_out;

    int n = out_size;  // 8,000,000 samples
    int blocks = (n + TILE - 1) / TILE;
    joint_cat_gather8<<<blocks, THREADS>>>(probs, X, out, n);
}

// round 10
// speedup vs baseline: 1.0443x; 1.0443x over previous
#include <cuda_runtime.h>
#include <cstdint>

// probs: float32 [50,50,50,50] -> 6,250,000 floats (row-major)
// X:     int32   [8,000,000, 4]
// out:   float32 [8,000,000]
//
// out[i] = probs[ ((X0*50 + X1)*50 + X2)*50 + X3 ]
//
// FINAL (best of R2-R9 sweep, = R5):
//  - quarter-warp predicated gathers: 8 active lanes per LDG shortens each
//    instruction's divergent-address replay chain, letting L1tex pipeline
//    wavefronts across instructions (R3->R4: measured win).
//  - __ldcg gathers (L2-only, no L1 fill/pollution), __ldcs X (streaming),
//    __stcs out (streaming)  (R4->R5: measured win).
//  - UNROLL=4 at 24 regs keeps occupancy ~86%; deeper ILP (UNROLL=8, 34 regs,
//    68% occ) measured strictly worse -- warp-parallelism > thread-ILP here.
//  - TMA X-feed, persistent pipelines, and cp.async gathers all measured
//    neutral or worse; ~44 us is the L1tex/L2 random-gather floor
//    (8M gathers x 32B L2 sectors on top of the 176 MB DRAM stream floor).

constexpr int THREADS = 256;
constexpr int UNROLL  = 4;
constexpr int TILE    = THREADS * UNROLL;  // 1024 samples per block

__global__ __launch_bounds__(THREADS) void joint_cat_gather_final(
    const float* __restrict__ probs,
    const int4* __restrict__ X,
    float* __restrict__ out,
    int n)
{
    int base = blockIdx.x * TILE + threadIdx.x;
    int lane_group = (threadIdx.x & 31) >> 3;   // 0..3

    if (base + (UNROLL - 1) * THREADS < n) {
        // ---- fast path: full tile ----
        int4 x[UNROLL];
#pragma unroll
        for (int k = 0; k < UNROLL; k++)
            x[k] = __ldcs(&X[base + k * THREADS]);     // streaming coalesced 16B loads

        int idx[UNROLL];
#pragma unroll
        for (int k = 0; k < UNROLL; k++)
            idx[k] = ((x[k].x * 50 + x[k].y) * 50 + x[k].z) * 50 + x[k].w;

        float r[UNROLL];
        // 16 predicated LDG.cg, each with 8 active lanes.
#pragma unroll
        for (int j = 0; j < 4; j++) {
#pragma unroll
            for (int k = 0; k < UNROLL; k++) {
                if (lane_group == j)
                    r[k] = __ldcg(probs + idx[k]);     // L2-only gather, no L1 fill
            }
        }

#pragma unroll
        for (int k = 0; k < UNROLL; k++)
            __stcs(&out[base + k * THREADS], r[k]);    // streaming coalesced stores
    } else {
        // ---- tail: per-element guard ----
#pragma unroll
        for (int k = 0; k < UNROLL; k++) {
            int i = base + k * THREADS;
            if (i < n) {
                int4 x = __ldcs(&X[i]);
                int idx = ((x.x * 50 + x.y) * 50 + x.z) * 50 + x.w;
                __stcs(&out[i], __ldcg(probs + idx));
            }
        }
    }
}

extern "C" void kernel_launch(void* const* d_in, const int* in_sizes, int n_in,
                              void* d_out, int out_size)
{
    const float* probs = (const float*)d_in[0];
    const int4* X = (const int4*)d_in[1];
    float* out = (float*)d_out;

    int n = out_size;  // 8,000,000 samples
    int blocks = (n + TILE - 1) / TILE;
    joint_cat_gather_final<<<blocks, THREADS>>>(probs, X, out, n);
}